// round 1
// baseline (speedup 1.0000x reference)
#include <cuda_runtime.h>
#include <math.h>

#define NN 120000
#define CC 80
#define KK 300
#define MAXDET 100
#define BB 2
#define SCORE_THRES 0.99875f
#define NMS_THRES 0.5f
#define MIN_SIZE 0.001f
#define BBOX_CLIP 4.135166556742356f
#define IMG_W 1216.0f
#define IMG_H 800.0f
#define CAND_CAP 2048

// Global scratch (no allocations allowed)
__device__ unsigned long long g_candKeys[BB][CAND_CAP];
__device__ int g_candCount[BB];

// -------- init: zero out5+keep, write labels, reset counters --------
__global__ void init_kernel(float* out) {
    const int total5 = BB * CC * KK * 5;   // 240000
    const int totalL = BB * CC * KK;       // 48000
    int stride = gridDim.x * blockDim.x;
    int gid = blockIdx.x * blockDim.x + threadIdx.x;
    for (int t = gid; t < total5; t += stride) out[t] = 0.0f;
    for (int t = gid; t < totalL; t += stride) {
        int c = (t % (CC * KK)) / KK;
        out[total5 + t] = (float)c;            // labels
        out[total5 + totalL + t] = 0.0f;       // keep
    }
    if (gid < BB) g_candCount[gid] = 0;
}

// -------- decode one anchor (matches reference exactly) --------
__device__ __forceinline__ float4 decode_box(const float* __restrict__ bp,
                                             const float* __restrict__ anc,
                                             int b, int n, bool* big) {
    float4 d = *(const float4*)(bp + ((size_t)b * NN + n) * 4);
    float4 a = *(const float4*)(anc + (size_t)n * 4);
    float wa = a.z - a.x;
    float ha = a.w - a.y;
    float cxa = a.x + 0.5f * wa;
    float cya = a.y + 0.5f * ha;
    float dw = fminf(d.z, BBOX_CLIP);
    float dh = fminf(d.w, BBOX_CLIP);
    float cx = d.x * wa + cxa;
    float cy = d.y * ha + cya;
    float w = expf(dw) * wa;
    float h = expf(dh) * ha;
    float x1 = fminf(fmaxf(cx - 0.5f * w, 0.0f), IMG_W);
    float y1 = fminf(fmaxf(cy - 0.5f * h, 0.0f), IMG_H);
    float x2 = fminf(fmaxf(cx + 0.5f * w, 0.0f), IMG_W);
    float y2 = fminf(fmaxf(cy + 0.5f * h, 0.0f), IMG_H);
    if (big) *big = (x2 - x1 >= MIN_SIZE) && (y2 - y1 >= MIN_SIZE);
    return make_float4(x1, y1, x2, y2);
}

// -------- gather class-0 candidates across the whole chip --------
__global__ void gather_kernel(const float* __restrict__ bp,
                              const float* __restrict__ cp,
                              const float* __restrict__ anc) {
    int stride = gridDim.x * blockDim.x;
    for (int t = blockIdx.x * blockDim.x + threadIdx.x; t < BB * NN; t += stride) {
        int b = t / NN;
        int n = t - b * NN;
        float sc = cp[((size_t)b * NN + n) * CC];   // class 0 score
        if (sc > SCORE_THRES) {
            bool big;
            (void)decode_box(bp, anc, b, n, &big);
            if (big) {
                int pos = atomicAdd(&g_candCount[b], 1);
                if (pos < CAND_CAP) {
                    unsigned long long key =
                        ((unsigned long long)__float_as_uint(sc) << 32) |
                        (unsigned long long)(0xFFFFFFFFu - (unsigned)n);
                    g_candKeys[b][pos] = key;
                }
            }
        }
    }
}

// -------- per-image sequential pipeline: sort / NMS / cap / class chain --------
__global__ void __launch_bounds__(1024) main_kernel(const float* __restrict__ bp,
                                                    const float* __restrict__ cp,
                                                    const float* __restrict__ anc,
                                                    float* __restrict__ out) {
    const int b = blockIdx.x;
    const int tid = threadIdx.x;

    __shared__ unsigned long long s_keys[CAND_CAP];
    __shared__ float s_sc[KK];
    __shared__ int   s_aidx[KK];
    __shared__ float4 s_box[KK];
    __shared__ int   s_keep[KK];
    __shared__ int   s_vidx[MAXDET + 4];
    __shared__ float4 s_vbox[MAXDET + 4];
    __shared__ int s_cnt;
    __shared__ int s_vcnt;

    float* out5 = out;                         // [B][C*K][5]
    float* outK = out + (size_t)BB * CC * KK * 5 + (size_t)BB * CC * KK;  // keep

    // ---- class 0: load candidate keys ----
    int m = g_candCount[b];
    if (m > CAND_CAP) m = CAND_CAP;
    for (int i = tid; i < m; i += blockDim.x) s_keys[i] = g_candKeys[b][i];
    __syncthreads();

    // rank sort (score desc, anchor idx asc) + scatter to top-K slots
    for (int i = tid; i < m; i += blockDim.x) {
        unsigned long long ki = s_keys[i];
        int rank = 0;
        for (int j = 0; j < m; j++) rank += (s_keys[j] > ki) ? 1 : 0;
        if (rank < KK) {
            int aidx = (int)(0xFFFFFFFFu - (unsigned)(ki & 0xFFFFFFFFull));
            s_sc[rank] = __uint_as_float((unsigned)(ki >> 32));
            s_aidx[rank] = aidx;
            s_box[rank] = decode_box(bp, anc, b, aidx, nullptr);
            s_keep[rank] = 1;
        }
    }
    int nTop = (m < KK) ? m : KK;
    __syncthreads();

    for (int c = 0;; c++) {
        // ---- greedy NMS (warp 0 only) + MAX_DET cap ----
        if (tid < 32) {
            for (int i = 0; i < nTop; i++) {
                __syncwarp();
                if (!s_keep[i]) continue;            // uniform across warp
                float4 bi = s_box[i];
                float ai = (bi.z - bi.x) * (bi.w - bi.y);
                for (int j = i + 1 + tid; j < nTop; j += 32) {
                    if (!s_keep[j]) continue;
                    float4 bj = s_box[j];
                    float aj = (bj.z - bj.x) * (bj.w - bj.y);
                    float lx = fmaxf(bi.x, bj.x);
                    float ly = fmaxf(bi.y, bj.y);
                    float rx = fminf(bi.z, bj.z);
                    float ry = fminf(bi.w, bj.w);
                    float iw = fmaxf(rx - lx, 0.0f);
                    float ih = fmaxf(ry - ly, 0.0f);
                    float inter = iw * ih;
                    float iou = inter / (ai + aj - inter + 1e-9f);
                    if (iou > NMS_THRES) s_keep[j] = 0;
                }
            }
            __syncwarp();
            if (tid == 0) {
                int cnt = 0;
                for (int r = 0; r < nTop; r++) {
                    if (s_keep[r]) {
                        if (cnt >= MAXDET) s_keep[r] = 0;
                        else cnt++;
                    }
                }
                s_vcnt = 0;
            }
        }
        __syncthreads();

        // ---- write outputs + rebuild valid set ----
        for (int r = tid; r < nTop; r += blockDim.x) {
            if (s_keep[r]) {
                size_t row = ((size_t)b * CC + c) * KK + r;
                float4 bx = s_box[r];
                out5[row * 5 + 0] = bx.x;
                out5[row * 5 + 1] = bx.y;
                out5[row * 5 + 2] = bx.z;
                out5[row * 5 + 3] = bx.w;
                out5[row * 5 + 4] = s_sc[r];
                outK[row] = 1.0f;
                int p = atomicAdd(&s_vcnt, 1);
                s_vidx[p] = s_aidx[r];
                s_vbox[p] = bx;
            }
        }
        __syncthreads();

        if (c == CC - 1) break;
        int vm = s_vcnt;
        if (vm == 0) break;   // valid set empty -> all later classes empty

        // ---- build candidates for class c+1 from valid set ----
        if (tid == 0) s_cnt = 0;
        __syncthreads();
        for (int i = tid; i < vm; i += blockDim.x) {
            int aidx = s_vidx[i];
            float sc = cp[((size_t)b * NN + aidx) * CC + (c + 1)];
            unsigned long long key = 0ull;
            if (sc > SCORE_THRES) {
                key = ((unsigned long long)__float_as_uint(sc) << 32) |
                      (unsigned long long)(0xFFFFFFFFu - (unsigned)aidx);
                atomicAdd(&s_cnt, 1);
            }
            s_keys[i] = key;
        }
        __syncthreads();
        int nc = s_cnt;
        for (int i = tid; i < vm; i += blockDim.x) {
            unsigned long long ki = s_keys[i];
            if (ki == 0ull) continue;
            int rank = 0;
            for (int j = 0; j < vm; j++) rank += (s_keys[j] > ki) ? 1 : 0;
            s_sc[rank] = __uint_as_float((unsigned)(ki >> 32));
            s_aidx[rank] = s_vidx[i];
            s_box[rank] = s_vbox[i];
            s_keep[rank] = 1;
        }
        nTop = nc;   // nc <= vm <= MAXDET < KK
        __syncthreads();
    }
}

extern "C" void kernel_launch(void* const* d_in, const int* in_sizes, int n_in,
                              void* d_out, int out_size) {
    const float* bp  = (const float*)d_in[0];  // box_preds  [B,N,4]
    const float* cp  = (const float*)d_in[1];  // cls_preds  [B,N,C]
    const float* anc = (const float*)d_in[2];  // anchors    [N,4]
    float* out = (float*)d_out;

    init_kernel<<<256, 256>>>(out);
    gather_kernel<<<(BB * NN + 255) / 256, 256>>>(bp, cp, anc);
    main_kernel<<<BB, 1024>>>(bp, cp, anc, out);
}

// round 2
// speedup vs baseline: 4.3196x; 4.3196x over previous
#include <cuda_runtime.h>
#include <math.h>

#define NN 120000
#define CC 80
#define KK 300
#define MAXDET 100
#define BB 2
#define SCORE_THRES 0.99875f
#define NMS_THRES 0.5f
#define MIN_SIZE 0.001f
#define BBOX_CLIP 4.135166556742356f
#define IMG_W 1216.0f
#define IMG_H 800.0f
#define CAND_CAP 2048
#define NW 5   // 5*64 = 320 bits >= KK=300

// Global scratch (no allocations allowed). Zero-initialized at module load;
// g_candCount is reset at the END of main_kernel for the next replay.
__device__ unsigned long long g_candKeys[BB][CAND_CAP];
__device__ float4 g_candBox[BB][CAND_CAP];
__device__ int g_candCount[BB];

// -------- decode one anchor (matches reference exactly) --------
__device__ __forceinline__ float4 decode_box(const float* __restrict__ bp,
                                             const float* __restrict__ anc,
                                             int b, int n, bool* big) {
    float4 d = *(const float4*)(bp + ((size_t)b * NN + n) * 4);
    float4 a = *(const float4*)(anc + (size_t)n * 4);
    float wa = a.z - a.x;
    float ha = a.w - a.y;
    float cxa = a.x + 0.5f * wa;
    float cya = a.y + 0.5f * ha;
    float dw = fminf(d.z, BBOX_CLIP);
    float dh = fminf(d.w, BBOX_CLIP);
    float cx = d.x * wa + cxa;
    float cy = d.y * ha + cya;
    float w = expf(dw) * wa;
    float h = expf(dh) * ha;
    float x1 = fminf(fmaxf(cx - 0.5f * w, 0.0f), IMG_W);
    float y1 = fminf(fmaxf(cy - 0.5f * h, 0.0f), IMG_H);
    float x2 = fminf(fmaxf(cx + 0.5f * w, 0.0f), IMG_W);
    float y2 = fminf(fmaxf(cy + 0.5f * h, 0.0f), IMG_H);
    if (big) *big = (x2 - x1 >= MIN_SIZE) && (y2 - y1 >= MIN_SIZE);
    return make_float4(x1, y1, x2, y2);
}

// -------- fused init + class-0 candidate gather (whole chip) --------
__global__ void gather_init_kernel(const float* __restrict__ bp,
                                   const float* __restrict__ cp,
                                   const float* __restrict__ anc,
                                   float* __restrict__ out) {
    const int total5 = BB * CC * KK * 5;   // 240000
    const int totalL = BB * CC * KK;       // 48000
    int stride = gridDim.x * blockDim.x;
    int gid = blockIdx.x * blockDim.x + threadIdx.x;

    // init outputs: out5 zeros, labels pattern, keep zeros
    for (int t = gid; t < total5; t += stride) out[t] = 0.0f;
    for (int t = gid; t < totalL; t += stride) {
        int c = (t % (CC * KK)) / KK;
        out[total5 + t] = (float)c;
        out[total5 + totalL + t] = 0.0f;
    }

    // gather class-0 candidates
    for (int t = gid; t < BB * NN; t += stride) {
        int b = t / NN;
        int n = t - b * NN;
        float sc = __ldg(cp + (size_t)t * CC);   // class-0 score
        if (sc > SCORE_THRES) {
            bool big;
            float4 bx = decode_box(bp, anc, b, n, &big);
            if (big) {
                int pos = atomicAdd(&g_candCount[b], 1);
                if (pos < CAND_CAP) {
                    unsigned long long key =
                        ((unsigned long long)__float_as_uint(sc) << 32) |
                        (unsigned long long)(0xFFFFFFFFu - (unsigned)n);
                    g_candKeys[b][pos] = key;
                    g_candBox[b][pos] = bx;
                }
            }
        }
    }
}

// -------- per-image: sort / parallel-bitmask NMS / cap / class chain --------
__global__ void __launch_bounds__(1024) main_kernel(const float* __restrict__ cp,
                                                    float* __restrict__ out) {
    const int b = blockIdx.x;
    const int tid = threadIdx.x;
    const int bd = blockDim.x;

    __shared__ unsigned long long s_keys[CAND_CAP];
    __shared__ unsigned long long s_mask[KK][NW];
    __shared__ unsigned long long s_keepw[NW];
    __shared__ int s_wpref[NW];
    __shared__ float4 s_box[KK];
    __shared__ float s_sc[KK];
    __shared__ int s_aidx[KK];
    __shared__ int s_vidx[MAXDET];
    __shared__ float4 s_vbox[MAXDET];
    __shared__ int s_cnt;
    __shared__ int s_vcnt;

    float* out5 = out;                                               // [B][C*K][5]
    float* outK = out + (size_t)BB * CC * KK * 5 + (size_t)BB * CC * KK;

    // ---- class 0 candidates ----
    int m = g_candCount[b];
    if (m > CAND_CAP) m = CAND_CAP;
    for (int i = tid; i < m; i += bd) s_keys[i] = g_candKeys[b][i];
    __syncthreads();

    // rank sort (score desc, anchor idx asc), scatter to top-K slots
    for (int i = tid; i < m; i += bd) {
        unsigned long long ki = s_keys[i];
        int rank = 0;
        for (int j = 0; j < m; j++) rank += (s_keys[j] > ki) ? 1 : 0;
        if (rank < KK) {
            s_sc[rank] = __uint_as_float((unsigned)(ki >> 32));
            s_aidx[rank] = (int)(0xFFFFFFFFu - (unsigned)(ki & 0xFFFFFFFFull));
            s_box[rank] = g_candBox[b][i];
        }
    }
    int nTop = (m < KK) ? m : KK;
    __syncthreads();

    for (int c = 0;; c++) {
        if (nTop > 0) {
            // ---- parallel suppression-mask build (all threads) ----
            int tasks = nTop * NW;
            for (int t = tid; t < tasks; t += bd) {
                int i = t / NW;
                int w = t - i * NW;
                float4 bi = s_box[i];
                float ai = (bi.z - bi.x) * (bi.w - bi.y);
                unsigned long long bits = 0ull;
                int jb = w * 64;
                int jend = jb + 64 < nTop ? jb + 64 : nTop;
                int jstart = (jb > i + 1) ? jb : i + 1;
                for (int j = jstart; j < jend; j++) {
                    float4 bj = s_box[j];
                    float aj = (bj.z - bj.x) * (bj.w - bj.y);
                    float lx = fmaxf(bi.x, bj.x);
                    float ly = fmaxf(bi.y, bj.y);
                    float rx = fminf(bi.z, bj.z);
                    float ry = fminf(bi.w, bj.w);
                    float iw = fmaxf(rx - lx, 0.0f);
                    float ih = fmaxf(ry - ly, 0.0f);
                    float inter = iw * ih;
                    float uni = ai + aj - inter + 1e-9f;
                    if (inter > NMS_THRES * uni) bits |= 1ull << (j - jb);
                }
                s_mask[i][w] = bits;
            }
            __syncthreads();

            // ---- sequential greedy pass + MAX_DET cap (thread 0, registers) ----
            if (tid == 0) {
                unsigned long long kw[NW];
                #pragma unroll
                for (int w = 0; w < NW; w++) {
                    int lo = w * 64;
                    int nn = nTop - lo;
                    kw[w] = (nn <= 0) ? 0ull : ((nn >= 64) ? ~0ull : ((1ull << nn) - 1ull));
                }
                #pragma unroll
                for (int w = 0; w < NW; w++) {
                    unsigned long long live = kw[w];
                    while (live) {
                        int bpos = __ffsll((long long)live) - 1;
                        int i = w * 64 + bpos;
                        #pragma unroll
                        for (int w2 = 0; w2 < NW; w2++) kw[w2] &= ~s_mask[i][w2];
                        live = (bpos == 63) ? 0ull
                             : (kw[w] & (~0ull << (bpos + 1)));
                    }
                }
                // MAX_DET cap: keep first 100 set bits
                int cnt = 0;
                #pragma unroll
                for (int w = 0; w < NW; w++) {
                    unsigned long long v = kw[w];
                    int pc = __popcll(v);
                    if (cnt >= MAXDET) v = 0ull;
                    else if (cnt + pc > MAXDET) {
                        int allowed = MAXDET - cnt;
                        unsigned long long r = v;
                        for (int q = 0; q < allowed; q++) r &= r - 1;
                        v &= ~r;
                        cnt = MAXDET;
                    } else cnt += pc;
                    s_keepw[w] = v;
                }
                int p = 0;
                #pragma unroll
                for (int w = 0; w < NW; w++) { s_wpref[w] = p; p += __popcll(s_keepw[w]); }
                s_vcnt = p;
            }
            __syncthreads();

            // ---- write outputs + rebuild valid set (prefix from bitmask) ----
            for (int r = tid; r < nTop; r += bd) {
                int w = r >> 6, bpos = r & 63;
                unsigned long long v = s_keepw[w];
                if ((v >> bpos) & 1ull) {
                    size_t row = ((size_t)b * CC + c) * KK + r;
                    float4 bx = s_box[r];
                    out5[row * 5 + 0] = bx.x;
                    out5[row * 5 + 1] = bx.y;
                    out5[row * 5 + 2] = bx.z;
                    out5[row * 5 + 3] = bx.w;
                    out5[row * 5 + 4] = s_sc[r];
                    outK[row] = 1.0f;
                    int p = s_wpref[w] + __popcll(v & ((1ull << bpos) - 1ull));
                    s_vidx[p] = s_aidx[r];
                    s_vbox[p] = bx;
                }
            }
            __syncthreads();
        } else {
            if (tid == 0) s_vcnt = 0;
            __syncthreads();
        }

        if (c == CC - 1) break;
        int vm = s_vcnt;
        if (vm == 0) break;   // valid set empty -> all later classes empty

        // ---- candidates for class c+1 from valid set ----
        if (tid == 0) s_cnt = 0;
        __syncthreads();
        for (int i = tid; i < vm; i += bd) {
            int aidx = s_vidx[i];
            float sc = cp[((size_t)b * NN + aidx) * CC + (c + 1)];
            unsigned long long key = 0ull;
            if (sc > SCORE_THRES) {
                key = ((unsigned long long)__float_as_uint(sc) << 32) |
                      (unsigned long long)(0xFFFFFFFFu - (unsigned)aidx);
                atomicAdd(&s_cnt, 1);
            }
            s_keys[i] = key;
        }
        __syncthreads();
        int nc = s_cnt;
        for (int i = tid; i < vm; i += bd) {
            unsigned long long ki = s_keys[i];
            if (ki == 0ull) continue;
            int rank = 0;
            for (int j = 0; j < vm; j++) rank += (s_keys[j] > ki) ? 1 : 0;
            s_sc[rank] = __uint_as_float((unsigned)(ki >> 32));
            s_aidx[rank] = s_vidx[i];
            s_box[rank] = s_vbox[i];
        }
        __syncthreads();
        nTop = nc;
        if (nTop == 0) break;  // nothing kept -> valid empties -> done
    }

    // reset candidate counter for the next graph replay (stream-ordered)
    __syncthreads();
    if (tid == 0) g_candCount[b] = 0;
}

extern "C" void kernel_launch(void* const* d_in, const int* in_sizes, int n_in,
                              void* d_out, int out_size) {
    const float* bp  = (const float*)d_in[0];  // box_preds  [B,N,4]
    const float* cp  = (const float*)d_in[1];  // cls_preds  [B,N,C]
    const float* anc = (const float*)d_in[2];  // anchors    [N,4]
    float* out = (float*)d_out;

    gather_init_kernel<<<(BB * NN + 255) / 256, 256>>>(bp, cp, anc, out);
    main_kernel<<<BB, 1024>>>(cp, out);
}

// round 3
// speedup vs baseline: 5.5838x; 1.2927x over previous
#include <cuda_runtime.h>
#include <math.h>

#define NN 120000
#define CC 80
#define KK 300
#define MAXDET 100
#define BB 2
#define SCORE_THRES 0.99875f
#define NMS_THRES 0.5f
#define MIN_SIZE 0.001f
#define BBOX_CLIP 4.135166556742356f
#define IMG_W 1216.0f
#define IMG_H 800.0f
#define CAND_CAP 2048
#define NW 5   // 5*64 = 320 bits >= KK=300

// Global scratch (no allocations allowed). Zero-initialized at module load;
// g_candCount is reset at the END of main_kernel for the next replay.
__device__ unsigned long long g_candKeys[BB][CAND_CAP];
__device__ float4 g_candBox[BB][CAND_CAP];
__device__ int g_candCount[BB];

// -------- decode one anchor (matches reference exactly) --------
__device__ __forceinline__ float4 decode_box(const float* __restrict__ bp,
                                             const float* __restrict__ anc,
                                             int b, int n, bool* big) {
    float4 d = *(const float4*)(bp + ((size_t)b * NN + n) * 4);
    float4 a = *(const float4*)(anc + (size_t)n * 4);
    float wa = a.z - a.x;
    float ha = a.w - a.y;
    float cxa = a.x + 0.5f * wa;
    float cya = a.y + 0.5f * ha;
    float dw = fminf(d.z, BBOX_CLIP);
    float dh = fminf(d.w, BBOX_CLIP);
    float cx = d.x * wa + cxa;
    float cy = d.y * ha + cya;
    float w = expf(dw) * wa;
    float h = expf(dh) * ha;
    float x1 = fminf(fmaxf(cx - 0.5f * w, 0.0f), IMG_W);
    float y1 = fminf(fmaxf(cy - 0.5f * h, 0.0f), IMG_H);
    float x2 = fminf(fmaxf(cx + 0.5f * w, 0.0f), IMG_W);
    float y2 = fminf(fmaxf(cy + 0.5f * h, 0.0f), IMG_H);
    if (big) *big = (x2 - x1 >= MIN_SIZE) && (y2 - y1 >= MIN_SIZE);
    return make_float4(x1, y1, x2, y2);
}

// -------- fused init + class-0 candidate gather (whole chip) --------
__global__ void gather_init_kernel(const float* __restrict__ bp,
                                   const float* __restrict__ cp,
                                   const float* __restrict__ anc,
                                   float* __restrict__ out) {
    const int total5 = BB * CC * KK * 5;   // 240000
    const int totalL = BB * CC * KK;       // 48000
    int stride = gridDim.x * blockDim.x;
    int gid = blockIdx.x * blockDim.x + threadIdx.x;

    for (int t = gid; t < total5; t += stride) out[t] = 0.0f;
    for (int t = gid; t < totalL; t += stride) {
        int c = (t % (CC * KK)) / KK;
        out[total5 + t] = (float)c;
        out[total5 + totalL + t] = 0.0f;
    }

    for (int t = gid; t < BB * NN; t += stride) {
        int b = t / NN;
        int n = t - b * NN;
        float sc = __ldg(cp + (size_t)t * CC);   // class-0 score
        if (sc > SCORE_THRES) {
            bool big;
            float4 bx = decode_box(bp, anc, b, n, &big);
            if (big) {
                int pos = atomicAdd(&g_candCount[b], 1);
                if (pos < CAND_CAP) {
                    unsigned long long key =
                        ((unsigned long long)__float_as_uint(sc) << 32) |
                        (unsigned long long)(0xFFFFFFFFu - (unsigned)n);
                    g_candKeys[b][pos] = key;
                    g_candBox[b][pos] = bx;
                }
            }
        }
    }
}

// -------- per-image: sort / parallel-bitmask NMS / cap / class chain --------
__global__ void __launch_bounds__(1024) main_kernel(const float* __restrict__ cp,
                                                    float* __restrict__ out) {
    const int b = blockIdx.x;
    const int tid = threadIdx.x;
    const int bd = blockDim.x;

    __shared__ unsigned long long s_keys[CAND_CAP];
    __shared__ unsigned long long s_mask[KK][NW];
    __shared__ unsigned long long s_nz[NW];       // rows with nonzero mask
    __shared__ unsigned long long s_keepw[NW];
    __shared__ int s_wpref[NW];
    __shared__ float4 s_box[KK];
    __shared__ float s_area[KK];
    __shared__ float s_sc[KK];
    __shared__ int s_aidx[KK];
    __shared__ int s_vidx[MAXDET];
    __shared__ float4 s_vbox[MAXDET];
    __shared__ int s_cnt;
    __shared__ int s_vcnt;

    float* out5 = out;                                               // [B][C*K][5]
    float* outK = out + (size_t)BB * CC * KK * 5 + (size_t)BB * CC * KK;

    // ---- class 0 candidates ----
    int m = g_candCount[b];
    if (m > CAND_CAP) m = CAND_CAP;
    for (int i = tid; i < m; i += bd) s_keys[i] = g_candKeys[b][i];
    __syncthreads();

    // rank sort (score desc, anchor idx asc), scatter to top-K slots
    for (int i = tid; i < m; i += bd) {
        unsigned long long ki = s_keys[i];
        int rank = 0;
        for (int j = 0; j < m; j++) rank += (s_keys[j] > ki) ? 1 : 0;
        if (rank < KK) {
            s_sc[rank] = __uint_as_float((unsigned)(ki >> 32));
            s_aidx[rank] = (int)(0xFFFFFFFFu - (unsigned)(ki & 0xFFFFFFFFull));
            float4 bx = g_candBox[b][i];
            s_box[rank] = bx;
            s_area[rank] = (bx.z - bx.x) * (bx.w - bx.y);
        }
    }
    int nTop = (m < KK) ? m : KK;
    __syncthreads();

    for (int c = 0;; c++) {
        if (nTop > 0) {
            if (tid < NW) s_nz[tid] = 0ull;
            __syncthreads();

            // ---- parallel suppression-mask build (all threads) ----
            int tasks = nTop * NW;
            for (int t = tid; t < tasks; t += bd) {
                int i = t / NW;
                int w = t - i * NW;
                float4 bi = s_box[i];
                float ai = s_area[i];
                unsigned long long bits = 0ull;
                int jb = w * 64;
                int jend = jb + 64 < nTop ? jb + 64 : nTop;
                int jstart = (jb > i + 1) ? jb : i + 1;
                for (int j = jstart; j < jend; j++) {
                    float4 bj = s_box[j];
                    float lx = fmaxf(bi.x, bj.x);
                    float ly = fmaxf(bi.y, bj.y);
                    float rx = fminf(bi.z, bj.z);
                    float ry = fminf(bi.w, bj.w);
                    float iw = fmaxf(rx - lx, 0.0f);
                    float ih = fmaxf(ry - ly, 0.0f);
                    float inter = iw * ih;
                    float uni = ai + s_area[j] - inter + 1e-9f;
                    if (inter > NMS_THRES * uni) bits |= 1ull << (j - jb);
                }
                s_mask[i][w] = bits;
                if (bits)
                    atomicOr(&s_nz[i >> 6], 1ull << (i & 63));
            }
            __syncthreads();

            // ---- sequential greedy pass over SUPPRESSOR rows only ----
            // (a row with an all-zero mask is a no-op in greedy NMS, kept or not)
            if (tid == 0) {
                unsigned long long kw[NW];
                #pragma unroll
                for (int w = 0; w < NW; w++) {
                    int nn = nTop - w * 64;
                    kw[w] = (nn <= 0) ? 0ull : ((nn >= 64) ? ~0ull : ((1ull << nn) - 1ull));
                }
                #pragma unroll
                for (int w = 0; w < NW; w++) {
                    unsigned long long live = kw[w] & s_nz[w];
                    while (live) {
                        int bpos = __ffsll((long long)live) - 1;
                        int i = w * 64 + bpos;
                        #pragma unroll
                        for (int w2 = 0; w2 < NW; w2++) kw[w2] &= ~s_mask[i][w2];
                        live = (bpos == 63) ? 0ull
                             : (kw[w] & s_nz[w] & (~0ull << (bpos + 1)));
                    }
                }
                // MAX_DET cap: keep first 100 set bits
                int cnt = 0;
                #pragma unroll
                for (int w = 0; w < NW; w++) {
                    unsigned long long v = kw[w];
                    int pc = __popcll(v);
                    if (cnt >= MAXDET) v = 0ull;
                    else if (cnt + pc > MAXDET) {
                        int allowed = MAXDET - cnt;
                        unsigned long long r = v;
                        for (int q = 0; q < allowed; q++) r &= r - 1;
                        v &= ~r;
                        cnt = MAXDET;
                    } else cnt += pc;
                    s_keepw[w] = v;
                }
                int p = 0;
                #pragma unroll
                for (int w = 0; w < NW; w++) { s_wpref[w] = p; p += __popcll(s_keepw[w]); }
                s_vcnt = p;
            }
            __syncthreads();

            // ---- write outputs + rebuild valid set (prefix from bitmask) ----
            for (int r = tid; r < nTop; r += bd) {
                int w = r >> 6, bpos = r & 63;
                unsigned long long v = s_keepw[w];
                if ((v >> bpos) & 1ull) {
                    size_t row = ((size_t)b * CC + c) * KK + r;
                    float4 bx = s_box[r];
                    out5[row * 5 + 0] = bx.x;
                    out5[row * 5 + 1] = bx.y;
                    out5[row * 5 + 2] = bx.z;
                    out5[row * 5 + 3] = bx.w;
                    out5[row * 5 + 4] = s_sc[r];
                    outK[row] = 1.0f;
                    int p = s_wpref[w] + __popcll(v & ((1ull << bpos) - 1ull));
                    s_vidx[p] = s_aidx[r];
                    s_vbox[p] = bx;
                }
            }
            __syncthreads();
        } else {
            if (tid == 0) s_vcnt = 0;
            __syncthreads();
        }

        if (c == CC - 1) break;
        int vm = s_vcnt;
        if (vm == 0) break;   // valid set empty -> all later classes empty

        // ---- candidates for class c+1 from valid set ----
        if (tid == 0) s_cnt = 0;
        __syncthreads();
        for (int i = tid; i < vm; i += bd) {
            int aidx = s_vidx[i];
            float sc = cp[((size_t)b * NN + aidx) * CC + (c + 1)];
            unsigned long long key = 0ull;
            if (sc > SCORE_THRES) {
                key = ((unsigned long long)__float_as_uint(sc) << 32) |
                      (unsigned long long)(0xFFFFFFFFu - (unsigned)aidx);
                atomicAdd(&s_cnt, 1);
            }
            s_keys[i] = key;
        }
        __syncthreads();
        int nc = s_cnt;
        for (int i = tid; i < vm; i += bd) {
            unsigned long long ki = s_keys[i];
            if (ki == 0ull) continue;
            int rank = 0;
            for (int j = 0; j < vm; j++) rank += (s_keys[j] > ki) ? 1 : 0;
            s_sc[rank] = __uint_as_float((unsigned)(ki >> 32));
            s_aidx[rank] = s_vidx[i];
            float4 bx = s_vbox[i];
            s_box[rank] = bx;
            s_area[rank] = (bx.z - bx.x) * (bx.w - bx.y);
        }
        __syncthreads();
        nTop = nc;
        if (nTop == 0) break;  // nothing kept -> valid empties -> done
    }

    // reset candidate counter for the next graph replay (stream-ordered)
    __syncthreads();
    if (tid == 0) g_candCount[b] = 0;
}

extern "C" void kernel_launch(void* const* d_in, const int* in_sizes, int n_in,
                              void* d_out, int out_size) {
    const float* bp  = (const float*)d_in[0];  // box_preds  [B,N,4]
    const float* cp  = (const float*)d_in[1];  // cls_preds  [B,N,C]
    const float* anc = (const float*)d_in[2];  // anchors    [N,4]
    float* out = (float*)d_out;

    gather_init_kernel<<<(BB * NN + 255) / 256, 256>>>(bp, cp, anc, out);
    main_kernel<<<BB, 1024>>>(cp, out);
}

// round 4
// speedup vs baseline: 6.1980x; 1.1100x over previous
#include <cuda_runtime.h>
#include <math.h>

#define NN 120000
#define CC 80
#define KK 300
#define MAXDET 100
#define BB 2
#define SCORE_THRES 0.99875f
#define NMS_THRES 0.5f
#define MIN_SIZE 0.001f
#define BBOX_CLIP 4.135166556742356f
#define IMG_W 1216.0f
#define IMG_H 800.0f
#define CAND_CAP 2048
#define NW 5   // 5*64 = 320 bits >= KK=300

// Global scratch (zero-initialized at load; g_candCount reset at end of main_kernel)
__device__ unsigned long long g_candKeys[BB][CAND_CAP];
__device__ float4 g_candBox[BB][CAND_CAP];
__device__ int g_candCount[BB];

// -------- decode one anchor (matches reference exactly) --------
__device__ __forceinline__ float4 decode_box(const float* __restrict__ bp,
                                             const float* __restrict__ anc,
                                             int b, int n, bool* big) {
    float4 d = *(const float4*)(bp + ((size_t)b * NN + n) * 4);
    float4 a = *(const float4*)(anc + (size_t)n * 4);
    float wa = a.z - a.x;
    float ha = a.w - a.y;
    float cxa = a.x + 0.5f * wa;
    float cya = a.y + 0.5f * ha;
    float dw = fminf(d.z, BBOX_CLIP);
    float dh = fminf(d.w, BBOX_CLIP);
    float cx = d.x * wa + cxa;
    float cy = d.y * ha + cya;
    float w = expf(dw) * wa;
    float h = expf(dh) * ha;
    float x1 = fminf(fmaxf(cx - 0.5f * w, 0.0f), IMG_W);
    float y1 = fminf(fmaxf(cy - 0.5f * h, 0.0f), IMG_H);
    float x2 = fminf(fmaxf(cx + 0.5f * w, 0.0f), IMG_W);
    float y2 = fminf(fmaxf(cy + 0.5f * h, 0.0f), IMG_H);
    if (big) *big = (x2 - x1 >= MIN_SIZE) && (y2 - y1 >= MIN_SIZE);
    return make_float4(x1, y1, x2, y2);
}

__device__ __forceinline__ bool iou_gt(float4 bi, float ai, float4 bj, float aj) {
    float lx = fmaxf(bi.x, bj.x);
    float ly = fmaxf(bi.y, bj.y);
    float rx = fminf(bi.z, bj.z);
    float ry = fminf(bi.w, bj.w);
    float iw = fmaxf(rx - lx, 0.0f);
    float ih = fmaxf(ry - ly, 0.0f);
    float inter = iw * ih;
    return inter > NMS_THRES * (ai + aj - inter + 1e-9f);
}

// -------- fused init + class-0 candidate gather (whole chip) --------
__global__ void gather_init_kernel(const float* __restrict__ bp,
                                   const float* __restrict__ cp,
                                   const float* __restrict__ anc,
                                   float* __restrict__ out) {
    const int total5 = BB * CC * KK * 5;   // 240000
    const int totalL = BB * CC * KK;       // 48000
    int stride = gridDim.x * blockDim.x;
    int gid = blockIdx.x * blockDim.x + threadIdx.x;

    for (int t = gid; t < total5; t += stride) out[t] = 0.0f;
    for (int t = gid; t < totalL; t += stride) {
        int c = (t % (CC * KK)) / KK;
        out[total5 + t] = (float)c;
        out[total5 + totalL + t] = 0.0f;
    }

    for (int t = gid; t < BB * NN; t += stride) {
        int b = t / NN;
        int n = t - b * NN;
        float sc = __ldg(cp + (size_t)t * CC);   // class-0 score
        if (sc > SCORE_THRES) {
            bool big;
            float4 bx = decode_box(bp, anc, b, n, &big);
            if (big) {
                int pos = atomicAdd(&g_candCount[b], 1);
                if (pos < CAND_CAP) {
                    unsigned long long key =
                        ((unsigned long long)__float_as_uint(sc) << 32) |
                        (unsigned long long)(0xFFFFFFFFu - (unsigned)n);
                    g_candKeys[b][pos] = key;
                    g_candBox[b][pos] = bx;
                }
            }
        }
    }
}

// -------- per-image: sort / warp-ballot NMS mask / greedy / class chain --------
__global__ void __launch_bounds__(1024) main_kernel(const float* __restrict__ cp,
                                                    float* __restrict__ out) {
    const int b = blockIdx.x;
    const int tid = threadIdx.x;
    const int bd = blockDim.x;   // 1024
    const int lane = tid & 31;
    const int warpId = tid >> 5;
    const int numWarps = bd >> 5;

    __shared__ unsigned long long s_keys[CAND_CAP];
    __shared__ unsigned long long s_mask[KK][NW];
    __shared__ unsigned long long s_nz[NW];
    __shared__ unsigned long long s_keepw[NW];
    __shared__ int s_wpref[NW];
    __shared__ float4 s_box[KK];
    __shared__ float s_area[KK];
    __shared__ float s_sc[KK];
    __shared__ int s_aidx[KK];
    __shared__ int s_vidx[MAXDET];
    __shared__ float4 s_vbox[MAXDET];
    __shared__ int s_cnt;
    __shared__ int s_vcnt;

    float* out5 = out;                                               // [B][C*K][5]
    float* outK = out + (size_t)BB * CC * KK * 5 + (size_t)BB * CC * KK;

    // ---- prologue: ONE concurrent memory round-trip (count + keys + boxes) ----
    int m = g_candCount[b];
    unsigned long long k0 = g_candKeys[b][tid];
    unsigned long long k1 = g_candKeys[b][tid + 1024];
    float4 bx0 = g_candBox[b][tid];
    float4 bx1 = g_candBox[b][tid + 1024];
    if (m > CAND_CAP) m = CAND_CAP;
    s_keys[tid]        = (tid < m)        ? k0 : 0ull;   // zeros => implicit pad
    s_keys[tid + 1024] = (tid + 1024 < m) ? k1 : 0ull;
    if (tid < NW) s_nz[tid] = 0ull;
    __syncthreads();

    // ---- rank sort (score desc, idx asc), vectorized key scan ----
    const ulonglong2* k2 = (const ulonglong2*)s_keys;
    int mPairs = (m + 1) >> 1;
    #pragma unroll
    for (int s = 0; s < 2; s++) {
        int i = tid + s * 1024;
        if (i < m) {
            unsigned long long ki = s ? k1 : k0;
            int rank = 0;
            for (int j = 0; j < mPairs; j++) {
                ulonglong2 kk = k2[j];
                rank += (kk.x > ki) + (kk.y > ki);
            }
            if (rank < KK) {
                s_sc[rank] = __uint_as_float((unsigned)(ki >> 32));
                s_aidx[rank] = (int)(0xFFFFFFFFu - (unsigned)(ki & 0xFFFFFFFFull));
                float4 bx = s ? bx1 : bx0;
                s_box[rank] = bx;
                s_area[rank] = (bx.z - bx.x) * (bx.w - bx.y);
            }
        }
    }
    int nTop = (m < KK) ? m : KK;
    __syncthreads();

    for (int c = 0;; c++) {
        if (nTop > 0) {
            // ---- warp-per-row ballot mask build ----
            int nwA = (nTop + 63) >> 6;
            for (int i = warpId; i < nTop; i += numWarps) {
                float4 bi = s_box[i];
                float ai = s_area[i];
                unsigned long long nzacc = 0ull;
                #pragma unroll
                for (int w = 0; w < NW; w++) {
                    unsigned long long bits = 0ull;
                    if (w < nwA) {
                        int j0 = (w << 6) + lane;
                        int j1 = j0 + 32;
                        bool o0 = false, o1 = false;
                        if (j0 > i && j0 < nTop) o0 = iou_gt(bi, ai, s_box[j0], s_area[j0]);
                        if (j1 > i && j1 < nTop) o1 = iou_gt(bi, ai, s_box[j1], s_area[j1]);
                        unsigned lo = __ballot_sync(0xFFFFFFFFu, o0);
                        unsigned hi = __ballot_sync(0xFFFFFFFFu, o1);
                        bits = ((unsigned long long)hi << 32) | (unsigned long long)lo;
                    }
                    if (lane == 0) {
                        s_mask[i][w] = bits;
                        nzacc |= bits;
                    }
                }
                if (lane == 0 && nzacc)
                    atomicOr(&s_nz[i >> 6], 1ull << (i & 63));
            }
            __syncthreads();

            // ---- sequential greedy over SUPPRESSOR rows only (thread 0) ----
            if (tid == 0) {
                unsigned long long kw[NW];
                #pragma unroll
                for (int w = 0; w < NW; w++) {
                    int nn = nTop - w * 64;
                    kw[w] = (nn <= 0) ? 0ull : ((nn >= 64) ? ~0ull : ((1ull << nn) - 1ull));
                }
                #pragma unroll
                for (int w = 0; w < NW; w++) {
                    unsigned long long live = kw[w] & s_nz[w];
                    while (live) {
                        int bpos = __ffsll((long long)live) - 1;
                        int i = w * 64 + bpos;
                        #pragma unroll
                        for (int w2 = 0; w2 < NW; w2++) kw[w2] &= ~s_mask[i][w2];
                        live = (bpos == 63) ? 0ull
                             : (kw[w] & s_nz[w] & (~0ull << (bpos + 1)));
                    }
                }
                // MAX_DET cap
                int cnt = 0;
                #pragma unroll
                for (int w = 0; w < NW; w++) {
                    unsigned long long v = kw[w];
                    int pc = __popcll(v);
                    if (cnt >= MAXDET) v = 0ull;
                    else if (cnt + pc > MAXDET) {
                        int allowed = MAXDET - cnt;
                        unsigned long long r = v;
                        for (int q = 0; q < allowed; q++) r &= r - 1;
                        v &= ~r;
                        cnt = MAXDET;
                    } else cnt += pc;
                    s_keepw[w] = v;
                }
                int p = 0;
                #pragma unroll
                for (int w = 0; w < NW; w++) { s_wpref[w] = p; p += __popcll(s_keepw[w]); }
                s_vcnt = p;
            }
            __syncthreads();

            // ---- write outputs + rebuild valid set ----
            for (int r = tid; r < nTop; r += bd) {
                int w = r >> 6, bpos = r & 63;
                unsigned long long v = s_keepw[w];
                if ((v >> bpos) & 1ull) {
                    size_t row = ((size_t)b * CC + c) * KK + r;
                    float4 bx = s_box[r];
                    out5[row * 5 + 0] = bx.x;
                    out5[row * 5 + 1] = bx.y;
                    out5[row * 5 + 2] = bx.z;
                    out5[row * 5 + 3] = bx.w;
                    out5[row * 5 + 4] = s_sc[r];
                    outK[row] = 1.0f;
                    int p = s_wpref[w] + __popcll(v & ((1ull << bpos) - 1ull));
                    s_vidx[p] = s_aidx[r];
                    s_vbox[p] = bx;
                }
            }
            __syncthreads();
        } else {
            if (tid == 0) s_vcnt = 0;
            __syncthreads();
        }

        if (c == CC - 1) break;
        int vm = s_vcnt;
        if (vm == 0) break;

        // ---- candidates for class c+1 from valid set (clear nz in same phase) ----
        if (tid == 0) s_cnt = 0;
        if (tid >= 32 && tid < 32 + NW) s_nz[tid - 32] = 0ull;
        __syncthreads();
        for (int i = tid; i < vm; i += bd) {
            int aidx = s_vidx[i];
            float sc = cp[((size_t)b * NN + aidx) * CC + (c + 1)];
            unsigned long long key = 0ull;
            if (sc > SCORE_THRES) {
                key = ((unsigned long long)__float_as_uint(sc) << 32) |
                      (unsigned long long)(0xFFFFFFFFu - (unsigned)aidx);
                atomicAdd(&s_cnt, 1);
            }
            s_keys[i] = key;
        }
        __syncthreads();
        int nc = s_cnt;
        for (int i = tid; i < vm; i += bd) {
            unsigned long long ki = s_keys[i];
            if (ki == 0ull) continue;
            int rank = 0;
            for (int j = 0; j < vm; j++) rank += (s_keys[j] > ki) ? 1 : 0;
            s_sc[rank] = __uint_as_float((unsigned)(ki >> 32));
            s_aidx[rank] = s_vidx[i];
            float4 bx = s_vbox[i];
            s_box[rank] = bx;
            s_area[rank] = (bx.z - bx.x) * (bx.w - bx.y);
        }
        __syncthreads();
        nTop = nc;
        if (nTop == 0) break;
    }

    // reset candidate counter for next graph replay (stream-ordered)
    __syncthreads();
    if (tid == 0) g_candCount[b] = 0;
}

extern "C" void kernel_launch(void* const* d_in, const int* in_sizes, int n_in,
                              void* d_out, int out_size) {
    const float* bp  = (const float*)d_in[0];  // box_preds  [B,N,4]
    const float* cp  = (const float*)d_in[1];  // cls_preds  [B,N,C]
    const float* anc = (const float*)d_in[2];  // anchors    [N,4]
    float* out = (float*)d_out;

    gather_init_kernel<<<(BB * NN + 255) / 256, 256>>>(bp, cp, anc, out);
    main_kernel<<<BB, 1024>>>(cp, out);
}